// round 4
// baseline (speedup 1.0000x reference)
#include <cuda_runtime.h>
#include <math.h>
#include <stdint.h>

#define NBLK 592
#define NTHR 256
#define TILE_INTS 2048           // 8KB tiles
#define TILE_BYTES 8192
#define TILE_V4 512
#define SAMP_BINS 1024
#define FINE_BINS 1024
#define MAX_POS (1 << 20)
#define POS_CAP 4096
#define SAMP_LO (-12.0f)
#define SAMP_W  (24.0f / SAMP_BINS)

static __device__ int                g_pos_n;
static __device__ int                g_pos_idx[MAX_POS];
static __device__ int                g_samp_hist[SAMP_BINS];
static __device__ float              g_Tlo, g_Thi;
static __device__ long long          g_nhns;
static __device__ unsigned long long g_cnt_above;
static __device__ double             g_loss_above, g_sig_above;
static __device__ int                g_fine_cnt[FINE_BINS];
static __device__ float              g_fine_loss[FINE_BINS];
static __device__ float              g_fine_sig[FINE_BINS];

__device__ __forceinline__ float softplus_acc(float x) {
    return fmaxf(x, 0.0f) + log1pf(__expf(-fabsf(x)));
}
__device__ __forceinline__ float softplus_fast(float x) {
    return fmaxf(x, 0.0f) + __logf(1.0f + __expf(-fabsf(x)));
}
__device__ __forceinline__ float sigm_fast(float x) {
    return __fdividef(1.0f, 1.0f + __expf(-x));
}

// ---- TMA 1D bulk + mbarrier helpers --------------------------------------
__device__ __forceinline__ uint32_t smaddr(const void* p) {
    return (uint32_t)__cvta_generic_to_shared(p);
}
__device__ __forceinline__ void mbar_init(uint32_t a, uint32_t cnt) {
    asm volatile("mbarrier.init.shared.b64 [%0], %1;" :: "r"(a), "r"(cnt) : "memory");
}
__device__ __forceinline__ void mbar_expect_tx(uint32_t a, uint32_t bytes) {
    asm volatile("mbarrier.arrive.expect_tx.shared.b64 _, [%0], %1;" :: "r"(a), "r"(bytes) : "memory");
}
__device__ __forceinline__ void bulk_g2s(uint32_t dst, const void* gsrc, uint32_t bytes, uint32_t mbar) {
    asm volatile(
        "cp.async.bulk.shared::cluster.global.mbarrier::complete_tx::bytes [%0], [%1], %2, [%3];"
        :: "r"(dst), "l"(gsrc), "r"(bytes), "r"(mbar) : "memory");
}
__device__ __forceinline__ void mbar_wait(uint32_t a, uint32_t parity) {
    asm volatile(
        "{\n\t"
        ".reg .pred P1;\n\t"
        "WAIT_LOOP_%=:\n\t"
        "mbarrier.try_wait.parity.acquire.cta.shared::cta.b64 P1, [%0], %1, 0x989680;\n\t"
        "@P1 bra.uni WAIT_DONE_%=;\n\t"
        "bra.uni WAIT_LOOP_%=;\n\t"
        "WAIT_DONE_%=:\n\t"
        "}"
        :: "r"(a), "r"(parity) : "memory");
}

// ---------------------------------------------------------------------------
__global__ void k_init() {
    int i = blockIdx.x * blockDim.x + threadIdx.x;
    if (i == 0) {
        g_pos_n = 0;
        g_cnt_above = 0ull;
        g_loss_above = 0.0;
        g_sig_above = 0.0;
    }
    if (i < SAMP_BINS) g_samp_hist[i] = 0;
    if (i < FINE_BINS) {
        g_fine_cnt[i] = 0;
        g_fine_loss[i] = 0.0f;
        g_fine_sig[i] = 0.0f;
    }
}

// ---------------------------------------------------------------------------
// Pass 1: (A) sampled coarse histogram (1/16 gather of preds+targs),
//         (B) TMA-stream targs; record positive INDICES, block-aggregated.
// ---------------------------------------------------------------------------
__global__ __launch_bounds__(NTHR) void k_pass1(
    const float4* __restrict__ preds4, const int4* __restrict__ targs4,
    const int* __restrict__ targs, int n)
{
    __shared__ alignas(128) int4 buf[2][TILE_V4];
    __shared__ uint64_t mbar[2];
    __shared__ int s_hist[SAMP_BINS];
    __shared__ int s_pos[POS_CAP];
    __shared__ int s_pcnt, s_base;

    const int tid = threadIdx.x;
    for (int i = tid; i < SAMP_BINS; i += NTHR) s_hist[i] = 0;
    if (tid == 0) {
        s_pcnt = 0;
        mbar_init(smaddr(&mbar[0]), 1);
        mbar_init(smaddr(&mbar[1]), 1);
        asm volatile("fence.proxy.async.shared::cta;" ::: "memory");
    }
    __syncthreads();

    const int n4 = n >> 2;
    const int TOT = gridDim.x * NTHR;

    // ---- phase A: sampled histogram, excluding positives ----
    {
        const float scale = (float)SAMP_BINS / 24.0f;
        for (int s = blockIdx.x * NTHR + tid; s < (n4 >> 4); s += TOT) {
            int idx4 = s << 4;           // idx4 & 15 == 0 : exactly 1/16
            float4 p = preds4[idx4];
            int4   t = targs4[idx4];
            if (!t.x) { int b = (int)((p.x - SAMP_LO) * scale); b = max(0, min(SAMP_BINS - 1, b)); atomicAdd(&s_hist[b], 1); }
            if (!t.y) { int b = (int)((p.y - SAMP_LO) * scale); b = max(0, min(SAMP_BINS - 1, b)); atomicAdd(&s_hist[b], 1); }
            if (!t.z) { int b = (int)((p.z - SAMP_LO) * scale); b = max(0, min(SAMP_BINS - 1, b)); atomicAdd(&s_hist[b], 1); }
            if (!t.w) { int b = (int)((p.w - SAMP_LO) * scale); b = max(0, min(SAMP_BINS - 1, b)); atomicAdd(&s_hist[b], 1); }
        }
    }

    // ---- phase B: TMA-streamed positive index collection ----
    const int ntiles = n / TILE_INTS;
    const int cnt = (ntiles > (int)blockIdx.x)
                    ? (ntiles - (int)blockIdx.x + (int)gridDim.x - 1) / (int)gridDim.x : 0;
    int ph[2] = {0, 0};

    if (cnt > 0 && tid == 0) {
        int tile0 = blockIdx.x;
        uint32_t mb = smaddr(&mbar[0]);
        mbar_expect_tx(mb, TILE_BYTES);
        bulk_g2s(smaddr(&buf[0][0]), (const char*)targs + (size_t)tile0 * TILE_BYTES, TILE_BYTES, mb);
    }

    for (int j = 0; j < cnt; j++) {
        if (j + 1 < cnt && tid == 0) {
            int tile = blockIdx.x + (j + 1) * gridDim.x;
            int b = (j + 1) & 1;
            uint32_t mb = smaddr(&mbar[b]);
            mbar_expect_tx(mb, TILE_BYTES);
            bulk_g2s(smaddr(&buf[b][0]), (const char*)targs + (size_t)tile * TILE_BYTES, TILE_BYTES, mb);
        }
        int b = j & 1;
        mbar_wait(smaddr(&mbar[b]), ph[b]);
        ph[b] ^= 1;

        int tile = blockIdx.x + j * gridDim.x;
        int ebase = tile * TILE_INTS;
        int4 a0 = buf[b][tid];
        int4 a1 = buf[b][tid + NTHR];
        if (a0.x | a0.y | a0.z | a0.w) {
            int e = ebase + tid * 4;
            if (a0.x) { int s = atomicAdd(&s_pcnt, 1); if (s < POS_CAP) s_pos[s] = e + 0; }
            if (a0.y) { int s = atomicAdd(&s_pcnt, 1); if (s < POS_CAP) s_pos[s] = e + 1; }
            if (a0.z) { int s = atomicAdd(&s_pcnt, 1); if (s < POS_CAP) s_pos[s] = e + 2; }
            if (a0.w) { int s = atomicAdd(&s_pcnt, 1); if (s < POS_CAP) s_pos[s] = e + 3; }
        }
        if (a1.x | a1.y | a1.z | a1.w) {
            int e = ebase + (tid + NTHR) * 4;
            if (a1.x) { int s = atomicAdd(&s_pcnt, 1); if (s < POS_CAP) s_pos[s] = e + 0; }
            if (a1.y) { int s = atomicAdd(&s_pcnt, 1); if (s < POS_CAP) s_pos[s] = e + 1; }
            if (a1.z) { int s = atomicAdd(&s_pcnt, 1); if (s < POS_CAP) s_pos[s] = e + 2; }
            if (a1.w) { int s = atomicAdd(&s_pcnt, 1); if (s < POS_CAP) s_pos[s] = e + 3; }
        }
        __syncthreads();   // all reads of buf[b] done before it is re-filled

        if (s_pcnt >= POS_CAP - TILE_INTS) {   // guarantee room for next tile
            int c0 = min(s_pcnt, POS_CAP);
            if (tid == 0) s_base = atomicAdd(&g_pos_n, c0);
            __syncthreads();
            for (int i = tid; i < c0; i += NTHR) {
                int d = s_base + i;
                if (d < MAX_POS) g_pos_idx[d] = s_pos[i];
            }
            __syncthreads();
            if (tid == 0) s_pcnt = 0;
            __syncthreads();
        }
    }

    // tail elements
    if (blockIdx.x == 0 && tid == 0) {
        for (int i = ntiles * TILE_INTS; i < n; i++) {
            if (targs[i]) { int id = atomicAdd(&g_pos_n, 1); if (id < MAX_POS) g_pos_idx[id] = i; }
        }
    }

    // final flush of positives (one global atomic per CTA)
    __syncthreads();
    {
        int c0 = min(s_pcnt, POS_CAP);
        if (c0 > 0) {
            if (tid == 0) s_base = atomicAdd(&g_pos_n, c0);
            __syncthreads();
            for (int i = tid; i < c0; i += NTHR) {
                int d = s_base + i;
                if (d < MAX_POS) g_pos_idx[d] = s_pos[i];
            }
        }
    }
    __syncthreads();
    for (int i = tid; i < SAMP_BINS; i += NTHR) {
        int c = s_hist[i];
        if (c) atomicAdd(&g_samp_hist[i], c);
    }
}

// ---------------------------------------------------------------------------
// Kernel 2 (1 block): compute n_hns, pick bracketing window [Tlo,Thi]
// ---------------------------------------------------------------------------
__global__ void k_pick(long long N) {
    __shared__ long long suf[SAMP_BINS];
    __shared__ int sh_bhi, sh_blo;
    int t = threadIdx.x;
    suf[t] = (long long)g_samp_hist[t];
    if (t == 0) { sh_bhi = SAMP_BINS; sh_blo = -1; }
    __syncthreads();
    for (int off = 1; off < SAMP_BINS; off <<= 1) {
        long long v = (t + off < SAMP_BINS) ? suf[t + off] : 0;
        __syncthreads();
        suf[t] += v;
        __syncthreads();
    }
    long long n_pos = min(g_pos_n, MAX_POS);
    long long n_neg = N - n_pos;
    long long nhns = (n_pos > 0) ? min(n_pos * 30LL, n_neg)
                                 : (long long)(0.1 * (double)n_neg);
    long long est = 16LL * suf[t];
    if (est * 100 <= nhns * 65)  atomicMin(&sh_bhi, t);
    if (est * 10  >= nhns * 15)  atomicMax(&sh_blo, t);
    __syncthreads();
    if (t == 0) {
        int bhi = sh_bhi, blo = sh_blo;
        if (bhi > SAMP_BINS - 1) bhi = SAMP_BINS - 1;
        if (bhi < 1) bhi = 1;
        if (blo < 0) blo = 0;
        if (blo >= bhi) blo = bhi - 1;
        g_Thi = SAMP_LO + (float)bhi * SAMP_W;
        g_Tlo = SAMP_LO + (float)blo * SAMP_W;
        g_nhns = nhns;
    }
}

// ---------------------------------------------------------------------------
// Pass 2: TMA-stream preds; exact sums above Thi (regs) + fine hist in SMEM
// ---------------------------------------------------------------------------
__global__ __launch_bounds__(NTHR) void k_pass2(
    const float* __restrict__ preds, int n)
{
    __shared__ alignas(128) float4 buf[2][TILE_V4];
    __shared__ uint64_t mbar[2];
    __shared__ int   s_cnt[FINE_BINS];
    __shared__ float s_loss[FINE_BINS];
    __shared__ float s_sig[FINE_BINS];
    __shared__ int   rc[NTHR];
    __shared__ float rl[NTHR], rs[NTHR];

    const int tid = threadIdx.x;
    for (int i = tid; i < FINE_BINS; i += NTHR) {
        s_cnt[i] = 0; s_loss[i] = 0.0f; s_sig[i] = 0.0f;
    }
    if (tid == 0) {
        mbar_init(smaddr(&mbar[0]), 1);
        mbar_init(smaddr(&mbar[1]), 1);
        asm volatile("fence.proxy.async.shared::cta;" ::: "memory");
    }
    __syncthreads();

    const float Tlo = g_Tlo, Thi = g_Thi;
    const float fscale = (float)FINE_BINS / (Thi - Tlo);
    int cnt = 0;
    float ls = 0.0f, ss = 0.0f;

    const int ntiles = n / TILE_INTS;
    const int tcount = (ntiles > (int)blockIdx.x)
                     ? (ntiles - (int)blockIdx.x + (int)gridDim.x - 1) / (int)gridDim.x : 0;
    int ph[2] = {0, 0};

    if (tcount > 0 && tid == 0) {
        uint32_t mb = smaddr(&mbar[0]);
        mbar_expect_tx(mb, TILE_BYTES);
        bulk_g2s(smaddr(&buf[0][0]), (const char*)preds + (size_t)blockIdx.x * TILE_BYTES, TILE_BYTES, mb);
    }

    for (int j = 0; j < tcount; j++) {
        if (j + 1 < tcount && tid == 0) {
            int tile = blockIdx.x + (j + 1) * gridDim.x;
            int b = (j + 1) & 1;
            uint32_t mb = smaddr(&mbar[b]);
            mbar_expect_tx(mb, TILE_BYTES);
            bulk_g2s(smaddr(&buf[b][0]), (const char*)preds + (size_t)tile * TILE_BYTES, TILE_BYTES, mb);
        }
        int b = j & 1;
        mbar_wait(smaddr(&mbar[b]), ph[b]);
        ph[b] ^= 1;

        float4 p0 = buf[b][tid];
        float4 p1 = buf[b][tid + NTHR];
        #pragma unroll
        for (int c = 0; c < 8; c++) {
            float v = (c < 4) ? ((c == 0) ? p0.x : (c == 1) ? p0.y : (c == 2) ? p0.z : p0.w)
                              : ((c == 4) ? p1.x : (c == 5) ? p1.y : (c == 6) ? p1.z : p1.w);
            if (v > Tlo) {
                float sp = softplus_fast(v);
                float sg = sigm_fast(v);
                if (v > Thi) {
                    cnt++; ls += sp; ss += sg;
                } else {
                    int fb = min((int)((v - Tlo) * fscale), FINE_BINS - 1);
                    atomicAdd(&s_cnt[fb], 1);
                    atomicAdd(&s_loss[fb], sp);
                    atomicAdd(&s_sig[fb], sg);
                }
            }
        }
        __syncthreads();
    }

    if (blockIdx.x == 0 && tid == 0) {
        for (int i = ntiles * TILE_INTS; i < n; i++) {
            float v = preds[i];
            if (v > Tlo) {
                float sp = softplus_fast(v);
                float sg = sigm_fast(v);
                if (v > Thi) { cnt++; ls += sp; ss += sg; }
                else {
                    int fb = min((int)((v - Tlo) * fscale), FINE_BINS - 1);
                    atomicAdd(&s_cnt[fb], 1);
                    atomicAdd(&s_loss[fb], sp);
                    atomicAdd(&s_sig[fb], sg);
                }
            }
        }
    }

    rc[tid] = cnt; rl[tid] = ls; rs[tid] = ss;
    __syncthreads();
    for (int off = NTHR / 2; off > 0; off >>= 1) {
        if (tid < off) { rc[tid] += rc[tid + off]; rl[tid] += rl[tid + off]; rs[tid] += rs[tid + off]; }
        __syncthreads();
    }
    if (tid == 0) {
        if (rc[0]) atomicAdd(&g_cnt_above, (unsigned long long)rc[0]);
        atomicAdd(&g_loss_above, (double)rl[0]);
        atomicAdd(&g_sig_above,  (double)rs[0]);
    }
    // merge fine histogram (skip empty bins)
    for (int i = tid; i < FINE_BINS; i += NTHR) {
        int c = s_cnt[i];
        if (c) {
            atomicAdd(&g_fine_cnt[i], c);
            atomicAdd(&g_fine_loss[i], s_loss[i]);
            atomicAdd(&g_fine_sig[i], s_sig[i]);
        }
    }
}

// ---------------------------------------------------------------------------
// Kernel 4 (1 block): gather positives, correct counters, exact threshold,
// final scalar
// ---------------------------------------------------------------------------
__global__ void k_final(const float* __restrict__ preds,
                        float* __restrict__ out, int out_size) {
    __shared__ int       s_cnt[FINE_BINS];
    __shared__ float     s_loss[FINE_BINS];
    __shared__ float     s_sig[FINE_BINS];
    __shared__ long long suf[FINE_BINS];
    __shared__ double    red1[1024], red2[1024];
    __shared__ int       sh_adj_cnt;
    __shared__ double    sh_adj_loss, sh_adj_sig;
    __shared__ int       sh_bstar;
    __shared__ float     sh_result;

    int t = threadIdx.x;
    s_cnt[t]  = g_fine_cnt[t];
    s_loss[t] = g_fine_loss[t];
    s_sig[t]  = g_fine_sig[t];
    if (t == 0) { sh_adj_cnt = 0; sh_adj_loss = 0.0; sh_adj_sig = 0.0; sh_bstar = -1; }
    __syncthreads();

    const float Tlo = g_Tlo, Thi = g_Thi;
    const float fscale = (float)FINE_BINS / (Thi - Tlo);
    int n_pos = min(g_pos_n, MAX_POS);

    double ploss = 0.0, psig = 0.0;
    for (int i = t; i < n_pos; i += blockDim.x) {
        float q  = preds[g_pos_idx[i]];
        float sp = softplus_acc(q);
        float sg = sigm_fast(q);
        ploss += (double)(sp - q);
        psig  += (double)sg;
        if (q > Thi) {
            float spf = softplus_fast(q);   // mirror pass2 fast math
            atomicAdd(&sh_adj_cnt, 1);
            atomicAdd(&sh_adj_loss, (double)spf);
            atomicAdd(&sh_adj_sig,  (double)sg);
        } else if (q > Tlo) {
            float spf = softplus_fast(q);
            int fb = min((int)((q - Tlo) * fscale), FINE_BINS - 1);
            atomicSub(&s_cnt[fb], 1);
            atomicAdd(&s_loss[fb], -spf);
            atomicAdd(&s_sig[fb],  -sg);
        }
    }
    red1[t] = ploss; red2[t] = psig;
    __syncthreads();
    for (int off = 512; off > 0; off >>= 1) {
        if (t < off) { red1[t] += red1[t + off]; red2[t] += red2[t + off]; }
        __syncthreads();
    }
    double pos_loss = red1[0];
    double pos_sig  = red2[0];
    __syncthreads();

    suf[t] = (long long)s_cnt[t];
    __syncthreads();
    for (int off = 1; off < FINE_BINS; off <<= 1) {
        long long v = (t + off < FINE_BINS) ? suf[t + off] : 0;
        __syncthreads();
        suf[t] += v;
        __syncthreads();
    }

    long long cnt_above = (long long)g_cnt_above - (long long)sh_adj_cnt;
    long long nhns = g_nhns;

    if (cnt_above + suf[t] >= nhns) atomicMax(&sh_bstar, t);
    __syncthreads();
    int bstar = sh_bstar;

    double fl = 0.0, fs = 0.0;
    if (t > bstar) { fl = (double)s_loss[t]; fs = (double)s_sig[t]; }
    red1[t] = fl; red2[t] = fs;
    __syncthreads();
    for (int off = 512; off > 0; off >>= 1) {
        if (t < off) { red1[t] += red1[t + off]; red2[t] += red2[t + off]; }
        __syncthreads();
    }

    if (t == 0) {
        double neg_loss = g_loss_above - sh_adj_loss + red1[0];
        double neg_sig  = g_sig_above  - sh_adj_sig  + red2[0];
        if (bstar >= 0 && bstar < FINE_BINS && s_cnt[bstar] > 0) {
            long long taken = cnt_above + (suf[bstar] - (long long)s_cnt[bstar]);
            long long r = nhns - taken;
            if (r < 0) r = 0;
            if (r > (long long)s_cnt[bstar]) r = (long long)s_cnt[bstar];
            double frac = (double)r / (double)s_cnt[bstar];
            neg_loss += frac * (double)s_loss[bstar];
            neg_sig  += frac * (double)s_sig[bstar];
        }
        double total_loss = neg_loss + pos_loss;
        double mean_loss  = total_loss / (double)(nhns + (long long)n_pos);
        double inter = pos_sig;
        double denom = neg_sig + pos_sig + (double)n_pos;
        double dice  = 1.0 - (2.0 * inter + 1e-10) / (denom + 1e-10);
        sh_result = (float)(dice + mean_loss);
    }
    __syncthreads();
    float r = sh_result;
    for (int i = t; i < out_size; i += blockDim.x) out[i] = r;
}

// ---------------------------------------------------------------------------
extern "C" void kernel_launch(void* const* d_in, const int* in_sizes, int n_in,
                              void* d_out, int out_size) {
    const float* preds = (const float*)d_in[0];
    const int*   targs = (const int*)d_in[1];
    int n = in_sizes[0];

    k_init<<<4, 256>>>();
    k_pass1<<<NBLK, NTHR>>>((const float4*)preds, (const int4*)targs, targs, n);
    k_pick<<<1, 1024>>>((long long)n);
    k_pass2<<<NBLK, NTHR>>>(preds, n);
    k_final<<<1, 1024>>>(preds, (float*)d_out, out_size);
}

// round 5
// speedup vs baseline: 1.4813x; 1.4813x over previous
#include <cuda_runtime.h>
#include <math.h>
#include <stdint.h>

#define NBLK 296                 // 2 CTAs/SM x 148 SMs
#define NTHR 256
#define STAGES 4
#define TILE_BYTES 16384         // 16KB per stage
#define TILE_ELEMS 4096          // 32-bit elements per tile
#define TILE_VEC4 1024           // vec4 per tile (= 4 * NTHR)
#define SAMP_BINS 1024
#define FINE_BINS 1024
#define MAX_POS (1 << 20)
#define POS_CAP (TILE_ELEMS + 1024)
#define SAMP_LO (-12.0f)
#define SAMP_W  (24.0f / SAMP_BINS)

static __device__ int                g_pos_n;
static __device__ int                g_pos_idx[MAX_POS];
static __device__ int                g_samp_hist[SAMP_BINS];
static __device__ float              g_Tlo, g_Thi;
static __device__ long long          g_nhns;
static __device__ unsigned long long g_cnt_above;
static __device__ double             g_loss_above, g_sig_above;
static __device__ int                g_fine_cnt[FINE_BINS];
static __device__ float              g_fine_loss[FINE_BINS];
static __device__ float              g_fine_sig[FINE_BINS];

__device__ __forceinline__ float softplus_acc(float x) {
    return fmaxf(x, 0.0f) + log1pf(__expf(-fabsf(x)));
}
__device__ __forceinline__ float softplus_fast(float x) {
    return fmaxf(x, 0.0f) + __logf(1.0f + __expf(-fabsf(x)));
}
__device__ __forceinline__ float sigm_fast(float x) {
    return __fdividef(1.0f, 1.0f + __expf(-x));
}

// ---- TMA 1D bulk + mbarrier helpers --------------------------------------
__device__ __forceinline__ uint32_t smaddr(const void* p) {
    return (uint32_t)__cvta_generic_to_shared(p);
}
__device__ __forceinline__ void mbar_init(uint32_t a, uint32_t cnt) {
    asm volatile("mbarrier.init.shared.b64 [%0], %1;" :: "r"(a), "r"(cnt) : "memory");
}
__device__ __forceinline__ void mbar_expect_tx(uint32_t a, uint32_t bytes) {
    asm volatile("mbarrier.arrive.expect_tx.shared.b64 _, [%0], %1;" :: "r"(a), "r"(bytes) : "memory");
}
__device__ __forceinline__ void bulk_g2s(uint32_t dst, const void* gsrc, uint32_t bytes, uint32_t mbar) {
    asm volatile(
        "cp.async.bulk.shared::cluster.global.mbarrier::complete_tx::bytes [%0], [%1], %2, [%3];"
        :: "r"(dst), "l"(gsrc), "r"(bytes), "r"(mbar) : "memory");
}
__device__ __forceinline__ void mbar_wait(uint32_t a, uint32_t parity) {
    asm volatile(
        "{\n\t"
        ".reg .pred P1;\n\t"
        "WAIT_LOOP_%=:\n\t"
        "mbarrier.try_wait.parity.acquire.cta.shared::cta.b64 P1, [%0], %1, 0x989680;\n\t"
        "@P1 bra.uni WAIT_DONE_%=;\n\t"
        "bra.uni WAIT_LOOP_%=;\n\t"
        "WAIT_DONE_%=:\n\t"
        "}"
        :: "r"(a), "r"(parity) : "memory");
}

// ---------------------------------------------------------------------------
__global__ void k_init() {
    int i = blockIdx.x * blockDim.x + threadIdx.x;
    if (i == 0) {
        g_pos_n = 0;
        g_cnt_above = 0ull;
        g_loss_above = 0.0;
        g_sig_above = 0.0;
    }
    if (i < SAMP_BINS) g_samp_hist[i] = 0;
    if (i < FINE_BINS) {
        g_fine_cnt[i] = 0;
        g_fine_loss[i] = 0.0f;
        g_fine_sig[i] = 0.0f;
    }
}

// ---------------------------------------------------------------------------
// Pass 1: (A) 1/16-sampled coarse histogram of negatives (gathered),
//         (B) 4-stage TMA stream of targs -> positive indices.
// ---------------------------------------------------------------------------
__global__ __launch_bounds__(NTHR) void k_pass1(
    const float4* __restrict__ preds4, const int4* __restrict__ targs4,
    const int* __restrict__ targs, int n)
{
    __shared__ alignas(128) int4 buf[STAGES][TILE_VEC4];   // 64KB
    __shared__ uint64_t mbar[STAGES];
    __shared__ int s_hist[SAMP_BINS];                       // 4KB
    __shared__ int s_pos[POS_CAP];                          // 20KB
    __shared__ int s_pcnt, s_base;

    const int tid = threadIdx.x;
    for (int i = tid; i < SAMP_BINS; i += NTHR) s_hist[i] = 0;
    if (tid == 0) {
        s_pcnt = 0;
        #pragma unroll
        for (int s = 0; s < STAGES; s++) mbar_init(smaddr(&mbar[s]), 1);
        asm volatile("fence.proxy.async.shared::cta;" ::: "memory");
    }
    __syncthreads();

    const int n4 = n >> 2;
    const int TOT = gridDim.x * NTHR;

    // ---- phase A: sampled histogram (negatives only) ----
    {
        const float scale = (float)SAMP_BINS / 24.0f;
        for (int s = blockIdx.x * NTHR + tid; s < (n4 >> 4); s += TOT) {
            int idx4 = s << 4;           // every 16th float4 => 1/16 of elements
            float4 p = preds4[idx4];
            int4   t = targs4[idx4];
            if (!t.x) { int b = (int)((p.x - SAMP_LO) * scale); b = max(0, min(SAMP_BINS - 1, b)); atomicAdd(&s_hist[b], 1); }
            if (!t.y) { int b = (int)((p.y - SAMP_LO) * scale); b = max(0, min(SAMP_BINS - 1, b)); atomicAdd(&s_hist[b], 1); }
            if (!t.z) { int b = (int)((p.z - SAMP_LO) * scale); b = max(0, min(SAMP_BINS - 1, b)); atomicAdd(&s_hist[b], 1); }
            if (!t.w) { int b = (int)((p.w - SAMP_LO) * scale); b = max(0, min(SAMP_BINS - 1, b)); atomicAdd(&s_hist[b], 1); }
        }
    }

    // ---- phase B: deep-pipelined TMA stream over targs ----
    const int ntiles = n / TILE_ELEMS;
    const int cnt = (ntiles > (int)blockIdx.x)
                    ? (ntiles - (int)blockIdx.x + (int)gridDim.x - 1) / (int)gridDim.x : 0;

    if (tid == 0) {
        #pragma unroll
        for (int s = 0; s < STAGES; s++) {
            if (s < cnt) {
                int tile = blockIdx.x + s * gridDim.x;
                uint32_t mb = smaddr(&mbar[s]);
                mbar_expect_tx(mb, TILE_BYTES);
                bulk_g2s(smaddr(&buf[s][0]), (const char*)targs + (size_t)tile * TILE_BYTES, TILE_BYTES, mb);
            }
        }
    }

    for (int j = 0; j < cnt; j++) {
        int b = j % STAGES;
        int parity = (j / STAGES) & 1;
        mbar_wait(smaddr(&mbar[b]), parity);

        int tile = blockIdx.x + j * gridDim.x;
        int ebase = tile * TILE_ELEMS;
        #pragma unroll
        for (int k = 0; k < 4; k++) {
            int v = tid + k * NTHR;
            int4 a = buf[b][v];
            if (a.x | a.y | a.z | a.w) {
                int e = ebase + v * 4;
                if (a.x) { int s = atomicAdd(&s_pcnt, 1); if (s < POS_CAP) s_pos[s] = e + 0; }
                if (a.y) { int s = atomicAdd(&s_pcnt, 1); if (s < POS_CAP) s_pos[s] = e + 1; }
                if (a.z) { int s = atomicAdd(&s_pcnt, 1); if (s < POS_CAP) s_pos[s] = e + 2; }
                if (a.w) { int s = atomicAdd(&s_pcnt, 1); if (s < POS_CAP) s_pos[s] = e + 3; }
            }
        }
        __syncthreads();   // buf[b] fully consumed

        if (s_pcnt > POS_CAP - TILE_ELEMS) {   // keep room for the next tile
            int c0 = min(s_pcnt, POS_CAP);
            if (tid == 0) s_base = atomicAdd(&g_pos_n, c0);
            __syncthreads();
            for (int i = tid; i < c0; i += NTHR) {
                int d = s_base + i;
                if (d < MAX_POS) g_pos_idx[d] = s_pos[i];
            }
            __syncthreads();
            if (tid == 0) s_pcnt = 0;
            __syncthreads();
        }

        if (tid == 0 && j + STAGES < cnt) {
            int tile2 = blockIdx.x + (j + STAGES) * gridDim.x;
            uint32_t mb = smaddr(&mbar[b]);
            mbar_expect_tx(mb, TILE_BYTES);
            bulk_g2s(smaddr(&buf[b][0]), (const char*)targs + (size_t)tile2 * TILE_BYTES, TILE_BYTES, mb);
        }
    }

    // tail elements
    if (blockIdx.x == 0 && tid == 0) {
        for (int i = ntiles * TILE_ELEMS; i < n; i++) {
            if (targs[i]) { int id = atomicAdd(&g_pos_n, 1); if (id < MAX_POS) g_pos_idx[id] = i; }
        }
    }

    // final flush
    __syncthreads();
    {
        int c0 = min(s_pcnt, POS_CAP);
        if (c0 > 0) {
            if (tid == 0) s_base = atomicAdd(&g_pos_n, c0);
            __syncthreads();
            for (int i = tid; i < c0; i += NTHR) {
                int d = s_base + i;
                if (d < MAX_POS) g_pos_idx[d] = s_pos[i];
            }
        }
    }
    __syncthreads();
    for (int i = tid; i < SAMP_BINS; i += NTHR) {
        int c = s_hist[i];
        if (c) atomicAdd(&g_samp_hist[i], c);
    }
}

// ---------------------------------------------------------------------------
// Kernel 2 (1 block): compute n_hns, pick bracketing window [Tlo,Thi]
// ---------------------------------------------------------------------------
__global__ void k_pick(long long N) {
    __shared__ long long suf[SAMP_BINS];
    __shared__ int sh_bhi, sh_blo;
    int t = threadIdx.x;
    suf[t] = (long long)g_samp_hist[t];
    if (t == 0) { sh_bhi = SAMP_BINS; sh_blo = -1; }
    __syncthreads();
    for (int off = 1; off < SAMP_BINS; off <<= 1) {
        long long v = (t + off < SAMP_BINS) ? suf[t + off] : 0;
        __syncthreads();
        suf[t] += v;
        __syncthreads();
    }
    long long n_pos = min(g_pos_n, MAX_POS);
    long long n_neg = N - n_pos;
    long long nhns = (n_pos > 0) ? min(n_pos * 30LL, n_neg)
                                 : (long long)(0.1 * (double)n_neg);
    long long est = 16LL * suf[t];
    if (est * 100 <= nhns * 65)  atomicMin(&sh_bhi, t);
    if (est * 10  >= nhns * 15)  atomicMax(&sh_blo, t);
    __syncthreads();
    if (t == 0) {
        int bhi = sh_bhi, blo = sh_blo;
        if (bhi > SAMP_BINS - 1) bhi = SAMP_BINS - 1;
        if (bhi < 1) bhi = 1;
        if (blo < 0) blo = 0;
        if (blo >= bhi) blo = bhi - 1;
        g_Thi = SAMP_LO + (float)bhi * SAMP_W;
        g_Tlo = SAMP_LO + (float)blo * SAMP_W;
        g_nhns = nhns;
    }
}

// ---------------------------------------------------------------------------
// Pass 2: 4-stage TMA stream of preds; sums above Thi + fine hist in SMEM
// ---------------------------------------------------------------------------
__global__ __launch_bounds__(NTHR) void k_pass2(
    const float* __restrict__ preds, int n)
{
    __shared__ alignas(128) float4 buf[STAGES][TILE_VEC4]; // 64KB
    __shared__ uint64_t mbar[STAGES];
    __shared__ int   s_cnt[FINE_BINS];
    __shared__ float s_loss[FINE_BINS];
    __shared__ float s_sig[FINE_BINS];
    __shared__ int   rc[NTHR];
    __shared__ float rl[NTHR], rs[NTHR];

    const int tid = threadIdx.x;
    for (int i = tid; i < FINE_BINS; i += NTHR) {
        s_cnt[i] = 0; s_loss[i] = 0.0f; s_sig[i] = 0.0f;
    }
    if (tid == 0) {
        #pragma unroll
        for (int s = 0; s < STAGES; s++) mbar_init(smaddr(&mbar[s]), 1);
        asm volatile("fence.proxy.async.shared::cta;" ::: "memory");
    }
    __syncthreads();

    const float Tlo = g_Tlo, Thi = g_Thi;
    const float fscale = (float)FINE_BINS / (Thi - Tlo);
    int cnt = 0;
    float ls = 0.0f, ss = 0.0f;

    const int ntiles = n / TILE_ELEMS;
    const int tcount = (ntiles > (int)blockIdx.x)
                     ? (ntiles - (int)blockIdx.x + (int)gridDim.x - 1) / (int)gridDim.x : 0;

    if (tid == 0) {
        #pragma unroll
        for (int s = 0; s < STAGES; s++) {
            if (s < tcount) {
                int tile = blockIdx.x + s * gridDim.x;
                uint32_t mb = smaddr(&mbar[s]);
                mbar_expect_tx(mb, TILE_BYTES);
                bulk_g2s(smaddr(&buf[s][0]), (const char*)preds + (size_t)tile * TILE_BYTES, TILE_BYTES, mb);
            }
        }
    }

    for (int j = 0; j < tcount; j++) {
        int b = j % STAGES;
        int parity = (j / STAGES) & 1;
        mbar_wait(smaddr(&mbar[b]), parity);

        #pragma unroll
        for (int k = 0; k < 4; k++) {
            float4 p = buf[b][tid + k * NTHR];
            #pragma unroll
            for (int c = 0; c < 4; c++) {
                float v = (c == 0) ? p.x : (c == 1) ? p.y : (c == 2) ? p.z : p.w;
                if (v > Tlo) {
                    float sp = softplus_fast(v);
                    float sg = sigm_fast(v);
                    if (v > Thi) {
                        cnt++; ls += sp; ss += sg;
                    } else {
                        int fb = min((int)((v - Tlo) * fscale), FINE_BINS - 1);
                        atomicAdd(&s_cnt[fb], 1);
                        atomicAdd(&s_loss[fb], sp);
                        atomicAdd(&s_sig[fb], sg);
                    }
                }
            }
        }
        __syncthreads();   // buf[b] fully consumed

        if (tid == 0 && j + STAGES < tcount) {
            int tile2 = blockIdx.x + (j + STAGES) * gridDim.x;
            uint32_t mb = smaddr(&mbar[b]);
            mbar_expect_tx(mb, TILE_BYTES);
            bulk_g2s(smaddr(&buf[b][0]), (const char*)preds + (size_t)tile2 * TILE_BYTES, TILE_BYTES, mb);
        }
    }

    if (blockIdx.x == 0 && tid == 0) {
        for (int i = ntiles * TILE_ELEMS; i < n; i++) {
            float v = preds[i];
            if (v > Tlo) {
                float sp = softplus_fast(v);
                float sg = sigm_fast(v);
                if (v > Thi) { cnt++; ls += sp; ss += sg; }
                else {
                    int fb = min((int)((v - Tlo) * fscale), FINE_BINS - 1);
                    atomicAdd(&s_cnt[fb], 1);
                    atomicAdd(&s_loss[fb], sp);
                    atomicAdd(&s_sig[fb], sg);
                }
            }
        }
    }

    rc[tid] = cnt; rl[tid] = ls; rs[tid] = ss;
    __syncthreads();
    for (int off = NTHR / 2; off > 0; off >>= 1) {
        if (tid < off) { rc[tid] += rc[tid + off]; rl[tid] += rl[tid + off]; rs[tid] += rs[tid + off]; }
        __syncthreads();
    }
    if (tid == 0) {
        if (rc[0]) atomicAdd(&g_cnt_above, (unsigned long long)rc[0]);
        atomicAdd(&g_loss_above, (double)rl[0]);
        atomicAdd(&g_sig_above,  (double)rs[0]);
    }
    for (int i = tid; i < FINE_BINS; i += NTHR) {
        int c = s_cnt[i];
        if (c) {
            atomicAdd(&g_fine_cnt[i], c);
            atomicAdd(&g_fine_loss[i], s_loss[i]);
            atomicAdd(&g_fine_sig[i], s_sig[i]);
        }
    }
}

// ---------------------------------------------------------------------------
// Kernel 4 (1 block): gather positives, correct counters, exact threshold,
// final scalar
// ---------------------------------------------------------------------------
__global__ void k_final(const float* __restrict__ preds,
                        float* __restrict__ out, int out_size) {
    __shared__ int       s_cnt[FINE_BINS];
    __shared__ float     s_loss[FINE_BINS];
    __shared__ float     s_sig[FINE_BINS];
    __shared__ long long suf[FINE_BINS];
    __shared__ double    red1[1024], red2[1024];
    __shared__ int       sh_adj_cnt;
    __shared__ double    sh_adj_loss, sh_adj_sig;
    __shared__ int       sh_bstar;
    __shared__ float     sh_result;

    int t = threadIdx.x;
    s_cnt[t]  = g_fine_cnt[t];
    s_loss[t] = g_fine_loss[t];
    s_sig[t]  = g_fine_sig[t];
    if (t == 0) { sh_adj_cnt = 0; sh_adj_loss = 0.0; sh_adj_sig = 0.0; sh_bstar = -1; }
    __syncthreads();

    const float Tlo = g_Tlo, Thi = g_Thi;
    const float fscale = (float)FINE_BINS / (Thi - Tlo);
    int n_pos = min(g_pos_n, MAX_POS);

    double ploss = 0.0, psig = 0.0;
    for (int i = t; i < n_pos; i += blockDim.x) {
        float q  = preds[g_pos_idx[i]];
        float sp = softplus_acc(q);
        float sg = sigm_fast(q);
        ploss += (double)(sp - q);
        psig  += (double)sg;
        if (q > Thi) {
            float spf = softplus_fast(q);   // mirror pass2 fast math
            atomicAdd(&sh_adj_cnt, 1);
            atomicAdd(&sh_adj_loss, (double)spf);
            atomicAdd(&sh_adj_sig,  (double)sg);
        } else if (q > Tlo) {
            float spf = softplus_fast(q);
            int fb = min((int)((q - Tlo) * fscale), FINE_BINS - 1);
            atomicSub(&s_cnt[fb], 1);
            atomicAdd(&s_loss[fb], -spf);
            atomicAdd(&s_sig[fb],  -sg);
        }
    }
    red1[t] = ploss; red2[t] = psig;
    __syncthreads();
    for (int off = 512; off > 0; off >>= 1) {
        if (t < off) { red1[t] += red1[t + off]; red2[t] += red2[t + off]; }
        __syncthreads();
    }
    double pos_loss = red1[0];
    double pos_sig  = red2[0];
    __syncthreads();

    suf[t] = (long long)s_cnt[t];
    __syncthreads();
    for (int off = 1; off < FINE_BINS; off <<= 1) {
        long long v = (t + off < FINE_BINS) ? suf[t + off] : 0;
        __syncthreads();
        suf[t] += v;
        __syncthreads();
    }

    long long cnt_above = (long long)g_cnt_above - (long long)sh_adj_cnt;
    long long nhns = g_nhns;

    if (cnt_above + suf[t] >= nhns) atomicMax(&sh_bstar, t);
    __syncthreads();
    int bstar = sh_bstar;

    double fl = 0.0, fs = 0.0;
    if (t > bstar) { fl = (double)s_loss[t]; fs = (double)s_sig[t]; }
    red1[t] = fl; red2[t] = fs;
    __syncthreads();
    for (int off = 512; off > 0; off >>= 1) {
        if (t < off) { red1[t] += red1[t + off]; red2[t] += red2[t + off]; }
        __syncthreads();
    }

    if (t == 0) {
        double neg_loss = g_loss_above - sh_adj_loss + red1[0];
        double neg_sig  = g_sig_above  - sh_adj_sig  + red2[0];
        if (bstar >= 0 && bstar < FINE_BINS && s_cnt[bstar] > 0) {
            long long taken = cnt_above + (suf[bstar] - (long long)s_cnt[bstar]);
            long long r = nhns - taken;
            if (r < 0) r = 0;
            if (r > (long long)s_cnt[bstar]) r = (long long)s_cnt[bstar];
            double frac = (double)r / (double)s_cnt[bstar];
            neg_loss += frac * (double)s_loss[bstar];
            neg_sig  += frac * (double)s_sig[bstar];
        }
        double total_loss = neg_loss + pos_loss;
        double mean_loss  = total_loss / (double)(nhns + (long long)n_pos);
        double inter = pos_sig;
        double denom = neg_sig + pos_sig + (double)n_pos;
        double dice  = 1.0 - (2.0 * inter + 1e-10) / (denom + 1e-10);
        sh_result = (float)(dice + mean_loss);
    }
    __syncthreads();
    float r = sh_result;
    for (int i = t; i < out_size; i += blockDim.x) out[i] = r;
}

// ---------------------------------------------------------------------------
extern "C" void kernel_launch(void* const* d_in, const int* in_sizes, int n_in,
                              void* d_out, int out_size) {
    const float* preds = (const float*)d_in[0];
    const int*   targs = (const int*)d_in[1];
    int n = in_sizes[0];

    k_init<<<4, 256>>>();
    k_pass1<<<NBLK, NTHR>>>((const float4*)preds, (const int4*)targs, targs, n);
    k_pick<<<1, 1024>>>((long long)n);
    k_pass2<<<NBLK, NTHR>>>(preds, n);
    k_final<<<1, 1024>>>(preds, (float*)d_out, out_size);
}